// round 12
// baseline (speedup 1.0000x reference)
#include <cuda_runtime.h>
#include <cuda_bf16.h>
#include <cstdint>

// NCCLayer argmax: 2-way bf16 split HMMA (3 chained MMAs) + exact rescue.
// R11 analysis: per-term HMMA ~7.6us, per-tile epilogue ~57us (binding).
// R12: single chained accumulator (no FADDs), warp-halves split D for 2x
// warps/SMSP, tight margin 4e-5 (bound ~1.5e-5), MLP'd rescue.

#define KK    16
#define DD    1024
#define NTOT  131072
#define TPB   512          // 16 warps: 8 row-groups x 2 d-halves
#define NBLK  (NTOT / 128)
#define MARGIN 4e-5f

__device__ __nv_bfloat16 g_as[2][NTOT * KK];   // A splits, n-major (8 MB)
__device__ __nv_bfloat16 g_bs[2][DD * KK];     // B splits, frag-packed (64 KB)
__device__ float g_bnorm[DD * KK];             // exact fp32 normalized b, [d][k]
__device__ int g_nflag;
__device__ int g_flaglist[NTOT];

// ---------------- prep: normalize + 2-way bf16 split ----------------
__device__ __forceinline__ void split2(float v, __nv_bfloat16& h1, __nv_bfloat16& h2) {
    h1 = __float2bfloat16(v);
    h2 = __float2bfloat16(v - __bfloat162float(h1));
}

__global__ __launch_bounds__(256) void prep_a_kernel(const float* __restrict__ x) {
    const int n = blockIdx.x * 256 + threadIdx.x;
    float a[KK];
    float s = 0.f;
    #pragma unroll
    for (int k = 0; k < KK; ++k) { a[k] = x[k * NTOT + n]; s += a[k]; }
    const float mu = s * (1.0f / KK);
    float ss = 0.f;
    #pragma unroll
    for (int k = 0; k < KK; ++k) { a[k] -= mu; ss += a[k] * a[k]; }
    const float inv = 1.0f / (sqrtf(ss) + 1e-10f);
    #pragma unroll
    for (int k = 0; k < KK; ++k) {
        __nv_bfloat16 h1, h2;
        split2(a[k] * inv, h1, h2);
        g_as[0][n * KK + k] = h1;
        g_as[1][n * KK + k] = h2;
    }
}

__global__ __launch_bounds__(256) void prep_b_kernel(const float* __restrict__ cmat) {
    if (blockIdx.x == 0 && threadIdx.x == 0) g_nflag = 0;  // reset per replay
    const int d = blockIdx.x * 256 + threadIdx.x;
    float b[KK];
    float s = 0.f;
    #pragma unroll
    for (int k = 0; k < KK; ++k) { b[k] = cmat[k * DD + d]; s += b[k]; }
    const float mu = s * (1.0f / KK);
    float ss = 0.f;
    #pragma unroll
    for (int k = 0; k < KK; ++k) { b[k] -= mu; ss += b[k] * b[k]; }
    const float inv = 1.0f / (sqrtf(ss) + 1e-10f);
    #pragma unroll
    for (int k = 0; k < KK; ++k) {
        const float bn = b[k] * inv;          // same op chain as R5 exact kernel
        g_bnorm[d * KK + k] = bn;
        __nv_bfloat16 h1, h2;
        split2(bn, h1, h2);
        // frag-packed: pair p = (k&7)>>1 holds slots {2p,2p+1,2p+8,2p+9}
        const int p    = (k & 7) >> 1;
        const int slot = ((k >> 3) << 1) | (k & 1);
        const int idx  = d * KK + p * 4 + slot;
        g_bs[0][idx] = h1;
        g_bs[1][idx] = h2;
    }
}

// ---------------- main: 3-term chained HMMA + top-2 + half-merge ----------------
__device__ __forceinline__ void mma16816(float& d0, float& d1, float& d2, float& d3,
                                         uint32_t a0, uint32_t a1, uint32_t a2,
                                         uint32_t a3, uint32_t b0, uint32_t b1) {
    asm volatile(
        "mma.sync.aligned.m16n8k16.row.col.f32.bf16.bf16.f32 "
        "{%0,%1,%2,%3}, {%4,%5,%6,%7}, {%8,%9}, {%0,%1,%2,%3};"
        : "+f"(d0), "+f"(d1), "+f"(d2), "+f"(d3)
        : "r"(a0), "r"(a1), "r"(a2), "r"(a3), "r"(b0), "r"(b1));
}

__global__ __launch_bounds__(TPB, 2) void ncc_hmma_kernel(float* __restrict__ out)
{
    extern __shared__ char smem[];   // B: 2 splits x 32 KB = 64 KB (merge buf aliases)

    const int tid = threadIdx.x;
    const int wid = tid >> 5;
    const int lid = tid & 31;
    const int t   = lid & 3;     // quad pos
    const int r   = lid >> 2;    // group row / B col
    const int g   = wid & 7;     // row group (16 rows each)
    const int h   = wid >> 3;    // d-half (0: cols 0..511, 1: 512..1023)

    // ---- Stage B into shared (bulk uint4 copy) ----
    {
        const uint4* src = (const uint4*)&g_bs[0][0];
        uint4* dst = (uint4*)smem;
        #pragma unroll
        for (int i = 0; i < (2 * DD * KK * 2) / 16 / TPB; ++i)
            dst[tid + i * TPB] = src[tid + i * TPB];
    }
    __syncthreads();

    // ---- A fragments (rows n0 = base+r, n1 = n0+8), 2 splits ----
    const int nbase = blockIdx.x * 128 + g * 16;
    const int n0 = nbase + r;
    const int n1 = n0 + 8;
    uint32_t af[2][4];
    #pragma unroll
    for (int s = 0; s < 2; ++s) {
        af[s][0] = *(const uint32_t*)&g_as[s][n0 * KK + 2 * t];
        af[s][1] = *(const uint32_t*)&g_as[s][n1 * KK + 2 * t];
        af[s][2] = *(const uint32_t*)&g_as[s][n0 * KK + 2 * t + 8];
        af[s][3] = *(const uint32_t*)&g_as[s][n1 * KK + 2 * t + 8];
    }

    float best0 = -3.0e38f, sec0 = -3.0e38f;
    float best1 = -3.0e38f, sec1 = -3.0e38f;
    int   bi0 = 0, bi1 = 0;

    const int dbase = h * 512;
    #pragma unroll 2
    for (int dtile = 0; dtile < 64; ++dtile) {
        const int dg = dbase + dtile * 8;

        // B fragments: one LDS.64 per split (frag-packed layout)
        uint32_t bf[2][2];
        #pragma unroll
        for (int s = 0; s < 2; ++s) {
            const uint64_t q = *(const uint64_t*)(smem + s * (DD * KK * 2)
                                                  + (dg + r) * (KK * 2) + t * 8);
            bf[s][0] = (uint32_t)q;
            bf[s][1] = (uint32_t)(q >> 32);
        }

        // single chained accumulator: small terms first, big last (no FADDs)
        float v0 = 0.f, v1 = 0.f, v2 = 0.f, v3 = 0.f;
        mma16816(v0, v1, v2, v3, af[1][0], af[1][1], af[1][2], af[1][3],
                 bf[0][0], bf[0][1]);                                  // a2*b1
        mma16816(v0, v1, v2, v3, af[0][0], af[0][1], af[0][2], af[0][3],
                 bf[1][0], bf[1][1]);                                  // a1*b2
        mma16816(v0, v1, v2, v3, af[0][0], af[0][1], af[0][2], af[0][3],
                 bf[0][0], bf[0][1]);                                  // a1*b1
        const int c0 = dg + 2 * t, c1 = c0 + 1;

        // branchless top-2 update, row n0
        {
            const float m01  = fmaxf(v0, v1);
            const float mn01 = fminf(v0, v1);
            const int   cm   = (v0 >= v1) ? c0 : c1;
            const bool  up   = m01 > best0;
            sec0  = up ? fmaxf(best0, mn01) : fmaxf(sec0, m01);
            bi0   = up ? cm : bi0;
            best0 = fmaxf(best0, m01);
        }
        // row n1
        {
            const float m01  = fmaxf(v2, v3);
            const float mn01 = fminf(v2, v3);
            const int   cm   = (v2 >= v3) ? c0 : c1;
            const bool  up   = m01 > best1;
            sec1  = up ? fmaxf(best1, mn01) : fmaxf(sec1, m01);
            bi1   = up ? cm : bi1;
            best1 = fmaxf(best1, m01);
        }
    }

    // ---- 4-lane butterfly: (best desc, idx asc), exact global second ----
    #pragma unroll
    for (int m = 1; m <= 2; m <<= 1) {
        float ob = __shfl_xor_sync(0xffffffffu, best0, m);
        float os = __shfl_xor_sync(0xffffffffu, sec0,  m);
        int   oi = __shfl_xor_sync(0xffffffffu, bi0,   m);
        float ns = fmaxf(fmaxf(fminf(best0, ob), sec0), os);
        if (ob > best0 || (ob == best0 && oi < bi0)) { best0 = ob; bi0 = oi; }
        sec0 = ns;

        ob = __shfl_xor_sync(0xffffffffu, best1, m);
        os = __shfl_xor_sync(0xffffffffu, sec1,  m);
        oi = __shfl_xor_sync(0xffffffffu, bi1,   m);
        ns = fmaxf(fmaxf(fminf(best1, ob), sec1), os);
        if (ob > best1 || (ob == best1 && oi < bi1)) { best1 = ob; bi1 = oi; }
        sec1 = ns;
    }

    // ---- merge the two d-halves via smem (aliases B; all reads done) ----
    __syncthreads();
    float4* buf = (float4*)smem;   // [2][128] {best, sec, idx, -}
    if (t == 0) {
        buf[h * 128 + g * 16 + r]     = make_float4(best0, sec0, (float)bi0, 0.f);
        buf[h * 128 + g * 16 + r + 8] = make_float4(best1, sec1, (float)bi1, 0.f);
    }
    __syncthreads();
    if (tid < 128) {
        const float4 m0 = buf[tid];        // half 0 (lower d) first => tie -> lower idx
        const float4 m1 = buf[128 + tid];
        const bool  w1   = m1.x > m0.x;
        const float best = w1 ? m1.x : m0.x;
        const float idx  = w1 ? m1.z : m0.z;
        const float sec  = fmaxf(fmaxf(fminf(m0.x, m1.x), m0.y), m1.y);
        const int n = blockIdx.x * 128 + tid;
        out[n] = idx;
        if (best - sec < MARGIN) {         // ambiguous (incl. ties) -> rescue
            const int j = atomicAdd(&g_nflag, 1);
            g_flaglist[j] = n;
        }
    }
}

// ---------------- rescue: exact R5 chain on precomputed bnorm ----------------
__global__ __launch_bounds__(256) void rescue_kernel(
    const float* __restrict__ x,
    float* __restrict__ out)
{
    const int warp  = (blockIdx.x * 256 + threadIdx.x) >> 5;
    const int lane  = threadIdx.x & 31;
    const int nwarp = (gridDim.x * 256) >> 5;
    const int count = g_nflag;

    for (int i = warp; i < count; i += nwarp) {
        const int n = g_flaglist[i];

        // a-normalization: identical op chain to the rel_err==0 R5 kernel
        float a[KK];
        float s = 0.f;
        #pragma unroll
        for (int k = 0; k < KK; ++k) { a[k] = x[k * NTOT + n]; s += a[k]; }
        const float mu = s * (1.0f / KK);
        float ss = 0.f;
        #pragma unroll
        for (int k = 0; k < KK; ++k) { a[k] -= mu; ss += a[k] * a[k]; }
        const float inv = 1.0f / (sqrtf(ss) + 1e-10f);
        #pragma unroll
        for (int k = 0; k < KK; ++k) a[k] *= inv;

        float best = -3.0e38f;
        int   bi   = 0;
        #pragma unroll 4
        for (int d0 = 0; d0 < DD; d0 += 32) {
            const int d = d0 + lane;
            const float4* bp = (const float4*)(&g_bnorm[d * KK]);  // L2-resident
            const float4 q0 = bp[0], q1 = bp[1], q2 = bp[2], q3 = bp[3];
            float acc = 0.f;
            acc = fmaf(a[0],  q0.x, acc); acc = fmaf(a[1],  q0.y, acc);
            acc = fmaf(a[2],  q0.z, acc); acc = fmaf(a[3],  q0.w, acc);
            acc = fmaf(a[4],  q1.x, acc); acc = fmaf(a[5],  q1.y, acc);
            acc = fmaf(a[6],  q1.z, acc); acc = fmaf(a[7],  q1.w, acc);
            acc = fmaf(a[8],  q2.x, acc); acc = fmaf(a[9],  q2.y, acc);
            acc = fmaf(a[10], q2.z, acc); acc = fmaf(a[11], q2.w, acc);
            acc = fmaf(a[12], q3.x, acc); acc = fmaf(a[13], q3.y, acc);
            acc = fmaf(a[14], q3.z, acc); acc = fmaf(a[15], q3.w, acc);
            if (acc > best) { best = acc; bi = d; }   // ascending d per lane
        }
        // 32-lane reduce: (value desc, index asc) == first occurrence
        #pragma unroll
        for (int m = 16; m >= 1; m >>= 1) {
            const float ov = __shfl_xor_sync(0xffffffffu, best, m);
            const int   oi = __shfl_xor_sync(0xffffffffu, bi,   m);
            if (ov > best || (ov == best && oi < bi)) { best = ov; bi = oi; }
        }
        if (lane == 0) out[n] = (float)bi;
    }
}

extern "C" void kernel_launch(void* const* d_in, const int* in_sizes, int n_in,
                              void* d_out, int out_size)
{
    // Select inputs by element count — immune to metadata ordering.
    const float* x;
    const float* cmat;
    if (in_sizes[0] >= in_sizes[1]) {
        x    = (const float*)d_in[0];
        cmat = (const float*)d_in[1];
    } else {
        x    = (const float*)d_in[1];
        cmat = (const float*)d_in[0];
    }
    float* out = (float*)d_out;

    prep_b_kernel<<<DD / 256, 256>>>(cmat);
    prep_a_kernel<<<NTOT / 256, 256>>>(x);

    const int smem = 2 * DD * KK * 2;   // 64 KB
    cudaFuncSetAttribute(ncc_hmma_kernel,
                         cudaFuncAttributeMaxDynamicSharedMemorySize, smem);
    ncc_hmma_kernel<<<NBLK, TPB, smem>>>(out);

    rescue_kernel<<<128, 256>>>(x, out);
}

// round 13
// speedup vs baseline: 1.5612x; 1.5612x over previous
#include <cuda_runtime.h>
#include <cuda_bf16.h>
#include <cstdint>

// NCCLayer argmax: 2-way bf16 split HMMA (3 INDEPENDENT MMAs) + in-CTA rescue.
// R12 lesson: chained MMAs serialize (HMMA legacy lat ~30cyc) => keep 3
// independent accumulators. B splits interleaved => 1 LDS.128/tile. Flagged
// rows (margin < 5e-5 > 2*err_bound 1.8e-5) rescued in-CTA with the verbatim
// R5 exact fp32 chain (rel_err 0.0 proven) -- no rescue kernel launch.

#define KK    16
#define DD    1024
#define NTOT  131072
#define TPB   256          // 8 warps, 128 n-rows per CTA
#define NBLK  (NTOT / 128)
#define MARGIN 5e-5f

__device__ __nv_bfloat16 g_as[2][NTOT * KK];   // A splits, n-major (8 MB)
__device__ __nv_bfloat16 g_bsp[DD * 32];       // B interleaved frag-pack (64 KB)
__device__ float g_bnorm[DD * KK];             // exact fp32 normalized b, [d][k]

// ---------------- prep: normalize + 2-way bf16 split ----------------
__device__ __forceinline__ void split2(float v, __nv_bfloat16& h1, __nv_bfloat16& h2) {
    h1 = __float2bfloat16(v);
    h2 = __float2bfloat16(v - __bfloat162float(h1));
}

__global__ __launch_bounds__(256) void prep_a_kernel(const float* __restrict__ x) {
    const int n = blockIdx.x * 256 + threadIdx.x;
    float a[KK];
    float s = 0.f;
    #pragma unroll
    for (int k = 0; k < KK; ++k) { a[k] = x[k * NTOT + n]; s += a[k]; }
    const float mu = s * (1.0f / KK);
    float ss = 0.f;
    #pragma unroll
    for (int k = 0; k < KK; ++k) { a[k] -= mu; ss += a[k] * a[k]; }
    const float inv = 1.0f / (sqrtf(ss) + 1e-10f);
    #pragma unroll
    for (int k = 0; k < KK; ++k) {
        __nv_bfloat16 h1, h2;
        split2(a[k] * inv, h1, h2);
        g_as[0][n * KK + k] = h1;
        g_as[1][n * KK + k] = h2;
    }
}

__global__ __launch_bounds__(256) void prep_b_kernel(const float* __restrict__ cmat) {
    const int d = blockIdx.x * 256 + threadIdx.x;
    float b[KK];
    float s = 0.f;
    #pragma unroll
    for (int k = 0; k < KK; ++k) { b[k] = cmat[k * DD + d]; s += b[k]; }
    const float mu = s * (1.0f / KK);
    float ss = 0.f;
    #pragma unroll
    for (int k = 0; k < KK; ++k) { b[k] -= mu; ss += b[k] * b[k]; }
    const float inv = 1.0f / (sqrtf(ss) + 1e-10f);
    #pragma unroll
    for (int k = 0; k < KK; ++k) {
        const float bn = b[k] * inv;          // same op chain as R5 exact kernel
        g_bnorm[d * KK + k] = bn;
        __nv_bfloat16 h1, h2;
        split2(bn, h1, h2);
        // interleaved frag-pack: per column d, per quad p (= (k&7)>>1):
        // 16B block = [split0 slots 0..3 | split1 slots 0..3],
        // slot = ((k>>3)<<1)|(k&1)  (covers k = {2p,2p+1,2p+8,2p+9})
        const int p    = (k & 7) >> 1;
        const int slot = ((k >> 3) << 1) | (k & 1);
        g_bsp[d * 32 + p * 8 + 0 + slot] = h1;   // split 0
        g_bsp[d * 32 + p * 8 + 4 + slot] = h2;   // split 1
    }
}

// ---------------- main: 3-term HMMA + top-2 + in-CTA exact rescue ----------------
__device__ __forceinline__ void mma16816(float& d0, float& d1, float& d2, float& d3,
                                         uint32_t a0, uint32_t a1, uint32_t a2,
                                         uint32_t a3, uint32_t b0, uint32_t b1) {
    asm volatile(
        "mma.sync.aligned.m16n8k16.row.col.f32.bf16.bf16.f32 "
        "{%0,%1,%2,%3}, {%4,%5,%6,%7}, {%8,%9}, {%0,%1,%2,%3};"
        : "+f"(d0), "+f"(d1), "+f"(d2), "+f"(d3)
        : "r"(a0), "r"(a1), "r"(a2), "r"(a3), "r"(b0), "r"(b1));
}

__global__ __launch_bounds__(TPB) void ncc_hmma_kernel(
    const float* __restrict__ x,
    float* __restrict__ out)
{
    extern __shared__ char smem[];   // B frag-pack: 64 KB (reused by rescue reduce)
    __shared__ int scount;
    __shared__ int sflag[128];

    const int tid = threadIdx.x;
    const int wid = tid >> 5;
    const int lid = tid & 31;
    const int t   = lid & 3;     // quad pos
    const int r   = lid >> 2;    // group row / B col

    if (tid == 0) scount = 0;

    // ---- Stage B frag-pack into shared (bulk uint4 copy) ----
    {
        const uint4* src = (const uint4*)&g_bsp[0];
        uint4* dst = (uint4*)smem;
        #pragma unroll
        for (int i = 0; i < (DD * 32 * 2) / 16 / TPB; ++i)
            dst[tid + i * TPB] = src[tid + i * TPB];
    }
    __syncthreads();

    // ---- A fragments (rows n0 = base+r, n1 = n0+8), 2 splits ----
    const int nbase = blockIdx.x * 128 + wid * 16;
    const int n0 = nbase + r;
    const int n1 = n0 + 8;
    uint32_t af[2][4];
    #pragma unroll
    for (int s = 0; s < 2; ++s) {
        af[s][0] = *(const uint32_t*)&g_as[s][n0 * KK + 2 * t];
        af[s][1] = *(const uint32_t*)&g_as[s][n1 * KK + 2 * t];
        af[s][2] = *(const uint32_t*)&g_as[s][n0 * KK + 2 * t + 8];
        af[s][3] = *(const uint32_t*)&g_as[s][n1 * KK + 2 * t + 8];
    }

    float best0 = -3.0e38f, sec0 = -3.0e38f;
    float best1 = -3.0e38f, sec1 = -3.0e38f;
    int   bi0 = 0, bi1 = 0;

    #pragma unroll 2
    for (int dtile = 0; dtile < DD / 8; ++dtile) {
        const int dg = dtile * 8;

        // ONE LDS.128: both splits' fragments for this (tile, quad)
        const uint4 q = *(const uint4*)(smem + (dg + r) * 64 + t * 16);

        // 3 INDEPENDENT MMA chains (ILP; combine with FADDs)
        float p0 = 0.f, p1 = 0.f, p2 = 0.f, p3 = 0.f;   // a1*b1
        float q0 = 0.f, q1 = 0.f, q2 = 0.f, q3 = 0.f;   // a1*b2
        float r0 = 0.f, r1 = 0.f, r2 = 0.f, r3 = 0.f;   // a2*b1
        mma16816(p0, p1, p2, p3, af[0][0], af[0][1], af[0][2], af[0][3], q.x, q.y);
        mma16816(q0, q1, q2, q3, af[0][0], af[0][1], af[0][2], af[0][3], q.z, q.w);
        mma16816(r0, r1, r2, r3, af[1][0], af[1][1], af[1][2], af[1][3], q.x, q.y);
        const float v0 = p0 + (q0 + r0), v1 = p1 + (q1 + r1);
        const float v2 = p2 + (q2 + r2), v3 = p3 + (q3 + r3);

        const int c0 = dg + 2 * t, c1 = c0 + 1;
        // branchless top-2 update, row n0
        {
            const float m01  = fmaxf(v0, v1);
            const float mn01 = fminf(v0, v1);
            const int   cm   = (v0 >= v1) ? c0 : c1;
            const bool  up   = m01 > best0;
            sec0  = up ? fmaxf(best0, mn01) : fmaxf(sec0, m01);
            bi0   = up ? cm : bi0;
            best0 = fmaxf(best0, m01);
        }
        // row n1
        {
            const float m01  = fmaxf(v2, v3);
            const float mn01 = fminf(v2, v3);
            const int   cm   = (v2 >= v3) ? c0 : c1;
            const bool  up   = m01 > best1;
            sec1  = up ? fmaxf(best1, mn01) : fmaxf(sec1, m01);
            bi1   = up ? cm : bi1;
            best1 = fmaxf(best1, m01);
        }
    }

    // ---- 4-lane butterfly: (best desc, idx asc), exact global second ----
    #pragma unroll
    for (int m = 1; m <= 2; m <<= 1) {
        float ob = __shfl_xor_sync(0xffffffffu, best0, m);
        float os = __shfl_xor_sync(0xffffffffu, sec0,  m);
        int   oi = __shfl_xor_sync(0xffffffffu, bi0,   m);
        float ns = fmaxf(fmaxf(fminf(best0, ob), sec0), os);
        if (ob > best0 || (ob == best0 && oi < bi0)) { best0 = ob; bi0 = oi; }
        sec0 = ns;

        ob = __shfl_xor_sync(0xffffffffu, best1, m);
        os = __shfl_xor_sync(0xffffffffu, sec1,  m);
        oi = __shfl_xor_sync(0xffffffffu, bi1,   m);
        ns = fmaxf(fmaxf(fminf(best1, ob), sec1), os);
        if (ob > best1 || (ob == best1 && oi < bi1)) { best1 = ob; bi1 = oi; }
        sec1 = ns;
    }

    if (t == 0) {
        out[n0] = (float)bi0;
        out[n1] = (float)bi1;
        if (best0 - sec0 < MARGIN) sflag[atomicAdd(&scount, 1)] = n0;
        if (best1 - sec1 < MARGIN) sflag[atomicAdd(&scount, 1)] = n1;
    }
    __syncthreads();

    // ---- in-CTA exact rescue for flagged rows (verbatim R5 fp32 chain) ----
    const int cnt = scount;
    if (cnt == 0) return;

    float* rval = (float*)smem;                 // aliases B staging (done with it)
    int*   ridx = (int*)(smem + TPB * 4);

    for (int f = 0; f < cnt; ++f) {
        const int n = sflag[f];

        // exact a-normalization (identical op chain to R5; broadcast loads)
        float a[KK];
        float s = 0.f;
        #pragma unroll
        for (int k = 0; k < KK; ++k) { a[k] = x[k * NTOT + n]; s += a[k]; }
        const float mu = s * (1.0f / KK);
        float ss = 0.f;
        #pragma unroll
        for (int k = 0; k < KK; ++k) { a[k] -= mu; ss += a[k] * a[k]; }
        const float inv = 1.0f / (sqrtf(ss) + 1e-10f);
        #pragma unroll
        for (int k = 0; k < KK; ++k) a[k] *= inv;

        // each thread: 4 columns, exact fmaf chain on precomputed bnorm
        float best = -3.0e38f;
        int   bi   = 0;
        #pragma unroll
        for (int j = 0; j < 4; ++j) {
            const int d = tid * 4 + j;          // ascending within thread
            const float4* bp = (const float4*)(&g_bnorm[d * KK]);
            const float4 w0 = bp[0], w1 = bp[1], w2 = bp[2], w3 = bp[3];
            float acc = 0.f;
            acc = fmaf(a[0],  w0.x, acc); acc = fmaf(a[1],  w0.y, acc);
            acc = fmaf(a[2],  w0.z, acc); acc = fmaf(a[3],  w0.w, acc);
            acc = fmaf(a[4],  w1.x, acc); acc = fmaf(a[5],  w1.y, acc);
            acc = fmaf(a[6],  w1.z, acc); acc = fmaf(a[7],  w1.w, acc);
            acc = fmaf(a[8],  w2.x, acc); acc = fmaf(a[9],  w2.y, acc);
            acc = fmaf(a[10], w2.z, acc); acc = fmaf(a[11], w2.w, acc);
            acc = fmaf(a[12], w3.x, acc); acc = fmaf(a[13], w3.y, acc);
            acc = fmaf(a[14], w3.z, acc); acc = fmaf(a[15], w3.w, acc);
            if (acc > best) { best = acc; bi = d; }   // strict > = first occurrence
        }
        rval[tid] = best;
        ridx[tid] = bi;
        __syncthreads();
        // block tree-reduce: (value desc, index asc)
        #pragma unroll
        for (int sdt = TPB / 2; sdt >= 1; sdt >>= 1) {
            if (tid < sdt) {
                const float ov = rval[tid + sdt];
                const int   oi = ridx[tid + sdt];
                if (ov > rval[tid] || (ov == rval[tid] && oi < ridx[tid])) {
                    rval[tid] = ov;
                    ridx[tid] = oi;
                }
            }
            __syncthreads();
        }
        if (tid == 0) out[n] = (float)ridx[0];
        __syncthreads();
    }
}

extern "C" void kernel_launch(void* const* d_in, const int* in_sizes, int n_in,
                              void* d_out, int out_size)
{
    // Select inputs by element count — immune to metadata ordering.
    const float* x;
    const float* cmat;
    if (in_sizes[0] >= in_sizes[1]) {
        x    = (const float*)d_in[0];
        cmat = (const float*)d_in[1];
    } else {
        x    = (const float*)d_in[1];
        cmat = (const float*)d_in[0];
    }
    float* out = (float*)d_out;

    prep_b_kernel<<<DD / 256, 256>>>(cmat);
    prep_a_kernel<<<NTOT / 256, 256>>>(x);

    const int smem = DD * 32 * 2;   // 64 KB
    cudaFuncSetAttribute(ncc_hmma_kernel,
                         cudaFuncAttributeMaxDynamicSharedMemorySize, smem);
    ncc_hmma_kernel<<<NBLK, TPB, smem>>>(x, out);
}

// round 14
// speedup vs baseline: 1.6745x; 1.0726x over previous
#include <cuda_runtime.h>
#include <cuda_bf16.h>
#include <cstdint>

// NCCLayer argmax: 2-way bf16 split HMMA + in-CTA exact rescue.
// R13 profiling: prep_b alone cost 12.4us (grid=4, latency). R14: single
// fused prep launch (A blocks + B blocks), small-term MMA pair chained
// (4 FADD/tile instead of 8; depth-2 chain == proven R11 structure),
// unroll-4 tile loop for epilogue ILP.

#define KK    16
#define DD    1024
#define NTOT  131072
#define TPB   256          // 8 warps, 128 n-rows per CTA
#define NBLK  (NTOT / 128)
#define MARGIN 5e-5f

__device__ __nv_bfloat16 g_as[2][NTOT * KK];   // A splits, n-major (8 MB)
__device__ __nv_bfloat16 g_bsp[DD * 32];       // B interleaved frag-pack (64 KB)
__device__ float g_bnorm[DD * KK];             // exact fp32 normalized b, [d][k]

// ---------------- fused prep: normalize + 2-way bf16 split ----------------
__device__ __forceinline__ void split2(float v, __nv_bfloat16& h1, __nv_bfloat16& h2) {
    h1 = __float2bfloat16(v);
    h2 = __float2bfloat16(v - __bfloat162float(h1));
}

__global__ __launch_bounds__(256) void prep_kernel(
    const float* __restrict__ x,
    const float* __restrict__ cmat)
{
    const int tid = threadIdx.x;
    if (blockIdx.x < NTOT / 256) {
        // ---- A side ----
        const int n = blockIdx.x * 256 + tid;
        float a[KK];
        float s = 0.f;
        #pragma unroll
        for (int k = 0; k < KK; ++k) { a[k] = x[k * NTOT + n]; s += a[k]; }
        const float mu = s * (1.0f / KK);
        float ss = 0.f;
        #pragma unroll
        for (int k = 0; k < KK; ++k) { a[k] -= mu; ss += a[k] * a[k]; }
        const float inv = 1.0f / (sqrtf(ss) + 1e-10f);
        #pragma unroll
        for (int k = 0; k < KK; ++k) {
            __nv_bfloat16 h1, h2;
            split2(a[k] * inv, h1, h2);
            g_as[0][n * KK + k] = h1;
            g_as[1][n * KK + k] = h2;
        }
    } else {
        // ---- B side ----
        const int d = (blockIdx.x - NTOT / 256) * 256 + tid;
        float b[KK];
        float s = 0.f;
        #pragma unroll
        for (int k = 0; k < KK; ++k) { b[k] = cmat[k * DD + d]; s += b[k]; }
        const float mu = s * (1.0f / KK);
        float ss = 0.f;
        #pragma unroll
        for (int k = 0; k < KK; ++k) { b[k] -= mu; ss += b[k] * b[k]; }
        const float inv = 1.0f / (sqrtf(ss) + 1e-10f);
        #pragma unroll
        for (int k = 0; k < KK; ++k) {
            const float bn = b[k] * inv;      // same op chain as R5 exact kernel
            g_bnorm[d * KK + k] = bn;
            __nv_bfloat16 h1, h2;
            split2(bn, h1, h2);
            // interleaved frag-pack: per column d, per quad p (= (k&7)>>1):
            // 16B block = [split0 slots 0..3 | split1 slots 0..3]
            const int p    = (k & 7) >> 1;
            const int slot = ((k >> 3) << 1) | (k & 1);
            g_bsp[d * 32 + p * 8 + 0 + slot] = h1;   // split 0
            g_bsp[d * 32 + p * 8 + 4 + slot] = h2;   // split 1
        }
    }
}

// ---------------- main: 3-term HMMA + top-2 + in-CTA exact rescue ----------------
__device__ __forceinline__ void mma16816(float& d0, float& d1, float& d2, float& d3,
                                         uint32_t a0, uint32_t a1, uint32_t a2,
                                         uint32_t a3, uint32_t b0, uint32_t b1) {
    asm volatile(
        "mma.sync.aligned.m16n8k16.row.col.f32.bf16.bf16.f32 "
        "{%0,%1,%2,%3}, {%4,%5,%6,%7}, {%8,%9}, {%0,%1,%2,%3};"
        : "+f"(d0), "+f"(d1), "+f"(d2), "+f"(d3)
        : "r"(a0), "r"(a1), "r"(a2), "r"(a3), "r"(b0), "r"(b1));
}

__global__ __launch_bounds__(TPB) void ncc_hmma_kernel(
    const float* __restrict__ x,
    float* __restrict__ out)
{
    extern __shared__ char smem[];   // B frag-pack: 64 KB (reused by rescue reduce)
    __shared__ int scount;
    __shared__ int sflag[128];

    const int tid = threadIdx.x;
    const int wid = tid >> 5;
    const int lid = tid & 31;
    const int t   = lid & 3;     // quad pos
    const int r   = lid >> 2;    // group row / B col

    if (tid == 0) scount = 0;

    // ---- Stage B frag-pack into shared (bulk uint4 copy) ----
    {
        const uint4* src = (const uint4*)&g_bsp[0];
        uint4* dst = (uint4*)smem;
        #pragma unroll
        for (int i = 0; i < (DD * 32 * 2) / 16 / TPB; ++i)
            dst[tid + i * TPB] = src[tid + i * TPB];
    }
    __syncthreads();

    // ---- A fragments (rows n0 = base+r, n1 = n0+8), 2 splits ----
    const int nbase = blockIdx.x * 128 + wid * 16;
    const int n0 = nbase + r;
    const int n1 = n0 + 8;
    uint32_t af[2][4];
    #pragma unroll
    for (int s = 0; s < 2; ++s) {
        af[s][0] = *(const uint32_t*)&g_as[s][n0 * KK + 2 * t];
        af[s][1] = *(const uint32_t*)&g_as[s][n1 * KK + 2 * t];
        af[s][2] = *(const uint32_t*)&g_as[s][n0 * KK + 2 * t + 8];
        af[s][3] = *(const uint32_t*)&g_as[s][n1 * KK + 2 * t + 8];
    }

    float best0 = -3.0e38f, sec0 = -3.0e38f;
    float best1 = -3.0e38f, sec1 = -3.0e38f;
    int   bi0 = 0, bi1 = 0;

    #pragma unroll 4
    for (int dtile = 0; dtile < DD / 8; ++dtile) {
        const int dg = dtile * 8;

        // ONE LDS.128: both splits' fragments for this (tile, quad)
        const uint4 q = *(const uint4*)(smem + (dg + r) * 64 + t * 16);

        // big term independent; two small terms chained (depth 2, tiny scale)
        float p0 = 0.f, p1 = 0.f, p2 = 0.f, p3 = 0.f;   // a1*b1
        float s0 = 0.f, s1 = 0.f, s2 = 0.f, s3 = 0.f;   // a1*b2 + a2*b1
        mma16816(p0, p1, p2, p3, af[0][0], af[0][1], af[0][2], af[0][3], q.x, q.y);
        mma16816(s0, s1, s2, s3, af[0][0], af[0][1], af[0][2], af[0][3], q.z, q.w);
        mma16816(s0, s1, s2, s3, af[1][0], af[1][1], af[1][2], af[1][3], q.x, q.y);
        const float v0 = p0 + s0, v1 = p1 + s1;
        const float v2 = p2 + s2, v3 = p3 + s3;

        const int c0 = dg + 2 * t, c1 = c0 + 1;
        // branchless top-2 update, row n0
        {
            const float m01  = fmaxf(v0, v1);
            const float mn01 = fminf(v0, v1);
            const int   cm   = (v0 >= v1) ? c0 : c1;
            const bool  up   = m01 > best0;
            sec0  = up ? fmaxf(best0, mn01) : fmaxf(sec0, m01);
            bi0   = up ? cm : bi0;
            best0 = fmaxf(best0, m01);
        }
        // row n1
        {
            const float m01  = fmaxf(v2, v3);
            const float mn01 = fminf(v2, v3);
            const int   cm   = (v2 >= v3) ? c0 : c1;
            const bool  up   = m01 > best1;
            sec1  = up ? fmaxf(best1, mn01) : fmaxf(sec1, m01);
            bi1   = up ? cm : bi1;
            best1 = fmaxf(best1, m01);
        }
    }

    // ---- 4-lane butterfly: (best desc, idx asc), exact global second ----
    #pragma unroll
    for (int m = 1; m <= 2; m <<= 1) {
        float ob = __shfl_xor_sync(0xffffffffu, best0, m);
        float os = __shfl_xor_sync(0xffffffffu, sec0,  m);
        int   oi = __shfl_xor_sync(0xffffffffu, bi0,   m);
        float ns = fmaxf(fmaxf(fminf(best0, ob), sec0), os);
        if (ob > best0 || (ob == best0 && oi < bi0)) { best0 = ob; bi0 = oi; }
        sec0 = ns;

        ob = __shfl_xor_sync(0xffffffffu, best1, m);
        os = __shfl_xor_sync(0xffffffffu, sec1,  m);
        oi = __shfl_xor_sync(0xffffffffu, bi1,   m);
        ns = fmaxf(fmaxf(fminf(best1, ob), sec1), os);
        if (ob > best1 || (ob == best1 && oi < bi1)) { best1 = ob; bi1 = oi; }
        sec1 = ns;
    }

    if (t == 0) {
        out[n0] = (float)bi0;
        out[n1] = (float)bi1;
        if (best0 - sec0 < MARGIN) sflag[atomicAdd(&scount, 1)] = n0;
        if (best1 - sec1 < MARGIN) sflag[atomicAdd(&scount, 1)] = n1;
    }
    __syncthreads();

    // ---- in-CTA exact rescue for flagged rows (verbatim R5 fp32 chain) ----
    const int cnt = scount;
    if (cnt == 0) return;

    float* rval = (float*)smem;                 // aliases B staging (done with it)
    int*   ridx = (int*)(smem + TPB * 4);

    for (int f = 0; f < cnt; ++f) {
        const int n = sflag[f];

        // exact a-normalization (identical op chain to R5; broadcast loads)
        float a[KK];
        float s = 0.f;
        #pragma unroll
        for (int k = 0; k < KK; ++k) { a[k] = x[k * NTOT + n]; s += a[k]; }
        const float mu = s * (1.0f / KK);
        float ss = 0.f;
        #pragma unroll
        for (int k = 0; k < KK; ++k) { a[k] -= mu; ss += a[k] * a[k]; }
        const float inv = 1.0f / (sqrtf(ss) + 1e-10f);
        #pragma unroll
        for (int k = 0; k < KK; ++k) a[k] *= inv;

        // each thread: 4 columns, exact fmaf chain on precomputed bnorm
        float best = -3.0e38f;
        int   bi   = 0;
        #pragma unroll
        for (int j = 0; j < 4; ++j) {
            const int d = tid * 4 + j;          // ascending within thread
            const float4* bp = (const float4*)(&g_bnorm[d * KK]);
            const float4 w0 = bp[0], w1 = bp[1], w2 = bp[2], w3 = bp[3];
            float acc = 0.f;
            acc = fmaf(a[0],  w0.x, acc); acc = fmaf(a[1],  w0.y, acc);
            acc = fmaf(a[2],  w0.z, acc); acc = fmaf(a[3],  w0.w, acc);
            acc = fmaf(a[4],  w1.x, acc); acc = fmaf(a[5],  w1.y, acc);
            acc = fmaf(a[6],  w1.z, acc); acc = fmaf(a[7],  w1.w, acc);
            acc = fmaf(a[8],  w2.x, acc); acc = fmaf(a[9],  w2.y, acc);
            acc = fmaf(a[10], w2.z, acc); acc = fmaf(a[11], w2.w, acc);
            acc = fmaf(a[12], w3.x, acc); acc = fmaf(a[13], w3.y, acc);
            acc = fmaf(a[14], w3.z, acc); acc = fmaf(a[15], w3.w, acc);
            if (acc > best) { best = acc; bi = d; }   // strict > = first occurrence
        }
        rval[tid] = best;
        ridx[tid] = bi;
        __syncthreads();
        // block tree-reduce: (value desc, index asc)
        #pragma unroll
        for (int sdt = TPB / 2; sdt >= 1; sdt >>= 1) {
            if (tid < sdt) {
                const float ov = rval[tid + sdt];
                const int   oi = ridx[tid + sdt];
                if (ov > rval[tid] || (ov == rval[tid] && oi < ridx[tid])) {
                    rval[tid] = ov;
                    ridx[tid] = oi;
                }
            }
            __syncthreads();
        }
        if (tid == 0) out[n] = (float)ridx[0];
        __syncthreads();
    }
}

extern "C" void kernel_launch(void* const* d_in, const int* in_sizes, int n_in,
                              void* d_out, int out_size)
{
    // Select inputs by element count — immune to metadata ordering.
    const float* x;
    const float* cmat;
    if (in_sizes[0] >= in_sizes[1]) {
        x    = (const float*)d_in[0];
        cmat = (const float*)d_in[1];
    } else {
        x    = (const float*)d_in[1];
        cmat = (const float*)d_in[0];
    }
    float* out = (float*)d_out;

    prep_kernel<<<NTOT / 256 + DD / 256, 256>>>(x, cmat);

    const int smem = DD * 32 * 2;   // 64 KB
    cudaFuncSetAttribute(ncc_hmma_kernel,
                         cudaFuncAttributeMaxDynamicSharedMemorySize, smem);
    ncc_hmma_kernel<<<NBLK, TPB, smem>>>(x, out);
}

// round 15
// speedup vs baseline: 1.9540x; 1.1669x over previous
#include <cuda_runtime.h>
#include <cuda_bf16.h>
#include <cstdint>

// NCCLayer argmax: 2-way bf16 split HMMA + mantissa-embedded-index argmax +
// in-CTA exact rescue. R14 profile: alu pipe 49% (top-2 ISETP/SEL chains).
// R15: bias dots by +4 (positive => uint-ordered), embed (255-position) in
// low 8 mantissa bits => FMNMX alone does argmax + first-occurrence ties.
// Quantization <= 1.22e-4 absorbed by MARGIN 3e-4 + exact rescue (proven).

#define KK    16
#define DD    1024
#define NTOT  131072
#define TPB   256          // 8 warps, 128 n-rows per CTA
#define NBLK  (NTOT / 128)
#define MARGINQ 3e-4f      // >= 2*delta_mma (3.2e-5) + 2*quant (1.22e-4)

__device__ __nv_bfloat16 g_as[2][NTOT * KK];   // A splits, n-major (8 MB)
__device__ __nv_bfloat16 g_bsp[DD * 32];       // B interleaved frag-pack (64 KB)
__device__ float g_bnorm[DD * KK];             // exact fp32 normalized b, [d][k]

// ---------------- fused prep: normalize + 2-way bf16 split ----------------
__device__ __forceinline__ void split2(float v, __nv_bfloat16& h1, __nv_bfloat16& h2) {
    h1 = __float2bfloat16(v);
    h2 = __float2bfloat16(v - __bfloat162float(h1));
}
__device__ __forceinline__ uint32_t pkbf(__nv_bfloat16 lo, __nv_bfloat16 hi) {
    return (uint32_t)__bfloat16_as_ushort(lo) | ((uint32_t)__bfloat16_as_ushort(hi) << 16);
}

__global__ __launch_bounds__(256) void prep_kernel(
    const float* __restrict__ x,
    const float* __restrict__ cmat)
{
    const int tid = threadIdx.x;
    if (blockIdx.x < NTOT / 256) {
        // ---- A side ----
        const int n = blockIdx.x * 256 + tid;
        float a[KK];
        float s = 0.f;
        #pragma unroll
        for (int k = 0; k < KK; ++k) { a[k] = x[k * NTOT + n]; s += a[k]; }
        const float mu = s * (1.0f / KK);
        float ss = 0.f;
        #pragma unroll
        for (int k = 0; k < KK; ++k) { a[k] -= mu; ss += a[k] * a[k]; }
        const float inv = 1.0f / (sqrtf(ss) + 1e-10f);
        __nv_bfloat16 h1[KK], h2[KK];
        #pragma unroll
        for (int k = 0; k < KK; ++k) split2(a[k] * inv, h1[k], h2[k]);
        uint4* d0 = (uint4*)&g_as[0][n * KK];
        uint4* d1 = (uint4*)&g_as[1][n * KK];
        d0[0] = make_uint4(pkbf(h1[0],h1[1]), pkbf(h1[2],h1[3]), pkbf(h1[4],h1[5]), pkbf(h1[6],h1[7]));
        d0[1] = make_uint4(pkbf(h1[8],h1[9]), pkbf(h1[10],h1[11]), pkbf(h1[12],h1[13]), pkbf(h1[14],h1[15]));
        d1[0] = make_uint4(pkbf(h2[0],h2[1]), pkbf(h2[2],h2[3]), pkbf(h2[4],h2[5]), pkbf(h2[6],h2[7]));
        d1[1] = make_uint4(pkbf(h2[8],h2[9]), pkbf(h2[10],h2[11]), pkbf(h2[12],h2[13]), pkbf(h2[14],h2[15]));
    } else {
        // ---- B side ----
        const int d = (blockIdx.x - NTOT / 256) * 256 + tid;
        float b[KK];
        float s = 0.f;
        #pragma unroll
        for (int k = 0; k < KK; ++k) { b[k] = cmat[k * DD + d]; s += b[k]; }
        const float mu = s * (1.0f / KK);
        float ss = 0.f;
        #pragma unroll
        for (int k = 0; k < KK; ++k) { b[k] -= mu; ss += b[k] * b[k]; }
        const float inv = 1.0f / (sqrtf(ss) + 1e-10f);
        float bn[KK];
        __nv_bfloat16 lb[32];
        #pragma unroll
        for (int k = 0; k < KK; ++k) {
            bn[k] = b[k] * inv;               // same op chain as R5 exact kernel
            __nv_bfloat16 h1, h2;
            split2(bn[k], h1, h2);
            // interleaved frag-pack: quad p = (k&7)>>1; 16B = [s0 x4 | s1 x4]
            const int p    = (k & 7) >> 1;
            const int slot = ((k >> 3) << 1) | (k & 1);
            lb[p * 8 + 0 + slot] = h1;
            lb[p * 8 + 4 + slot] = h2;
        }
        float4* fb = (float4*)&g_bnorm[d * KK];
        fb[0] = make_float4(bn[0], bn[1], bn[2], bn[3]);
        fb[1] = make_float4(bn[4], bn[5], bn[6], bn[7]);
        fb[2] = make_float4(bn[8], bn[9], bn[10], bn[11]);
        fb[3] = make_float4(bn[12], bn[13], bn[14], bn[15]);
        uint4* ob = (uint4*)&g_bsp[d * 32];
        #pragma unroll
        for (int q = 0; q < 4; ++q)
            ob[q] = make_uint4(pkbf(lb[q*8+0],lb[q*8+1]), pkbf(lb[q*8+2],lb[q*8+3]),
                               pkbf(lb[q*8+4],lb[q*8+5]), pkbf(lb[q*8+6],lb[q*8+7]));
    }
}

// ---------------- main: HMMA + embedded-index top-2 + in-CTA rescue ----------------
__device__ __forceinline__ void mma16816(float& d0, float& d1, float& d2, float& d3,
                                         uint32_t a0, uint32_t a1, uint32_t a2,
                                         uint32_t a3, uint32_t b0, uint32_t b1) {
    asm volatile(
        "mma.sync.aligned.m16n8k16.row.col.f32.bf16.bf16.f32 "
        "{%0,%1,%2,%3}, {%4,%5,%6,%7}, {%8,%9}, {%0,%1,%2,%3};"
        : "+f"(d0), "+f"(d1), "+f"(d2), "+f"(d3)
        : "r"(a0), "r"(a1), "r"(a2), "r"(a3), "r"(b0), "r"(b1));
}

// embed code into low 8 mantissa bits of biased-positive value
__device__ __forceinline__ float embed(float v, uint32_t code) {
    return __uint_as_float((__float_as_uint(v + 4.0f) & 0xFFFFFF00u) | code);
}

__global__ __launch_bounds__(TPB) void ncc_hmma_kernel(
    const float* __restrict__ x,
    float* __restrict__ out)
{
    extern __shared__ char smem[];   // B frag-pack: 64 KB (reused by rescue reduce)
    __shared__ int scount;
    __shared__ int sflag[128];

    const int tid = threadIdx.x;
    const int wid = tid >> 5;
    const int lid = tid & 31;
    const int t   = lid & 3;     // quad pos
    const int r   = lid >> 2;    // group row / B col

    if (tid == 0) scount = 0;

    // ---- Stage B frag-pack into shared ----
    {
        const uint4* src = (const uint4*)&g_bsp[0];
        uint4* dst = (uint4*)smem;
        #pragma unroll
        for (int i = 0; i < (DD * 32 * 2) / 16 / TPB; ++i)
            dst[tid + i * TPB] = src[tid + i * TPB];
    }
    __syncthreads();

    // ---- A fragments (rows n0 = base+r, n1 = n0+8), 2 splits ----
    const int nbase = blockIdx.x * 128 + wid * 16;
    const int n0 = nbase + r;
    const int n1 = n0 + 8;
    uint32_t af[2][4];
    #pragma unroll
    for (int s = 0; s < 2; ++s) {
        af[s][0] = *(const uint32_t*)&g_as[s][n0 * KK + 2 * t];
        af[s][1] = *(const uint32_t*)&g_as[s][n1 * KK + 2 * t];
        af[s][2] = *(const uint32_t*)&g_as[s][n0 * KK + 2 * t + 8];
        af[s][3] = *(const uint32_t*)&g_as[s][n1 * KK + 2 * t + 8];
    }

    // embedded running top-2 per row (positive domain; 0.0 < any value)
    float best0 = 0.f, sec0 = 0.f;
    float best1 = 0.f, sec1 = 0.f;

    #pragma unroll 4
    for (int dt2 = 0; dt2 < 64; ++dt2) {     // 2 tiles per iteration
        const int dg = dt2 * 16;
        const uint32_t cb = 255u - 4u * (uint32_t)dt2;   // codes cb, cb-1, cb-2, cb-3

        const uint4 qa = *(const uint4*)(smem + (dg + r) * 64 + t * 16);
        const uint4 qb = *(const uint4*)(smem + (dg + 8 + r) * 64 + t * 16);

        float pa0=0.f,pa1=0.f,pa2=0.f,pa3=0.f, sa0=0.f,sa1=0.f,sa2=0.f,sa3=0.f;
        float pb0=0.f,pb1=0.f,pb2=0.f,pb3=0.f, sb0=0.f,sb1=0.f,sb2=0.f,sb3=0.f;
        mma16816(pa0,pa1,pa2,pa3, af[0][0],af[0][1],af[0][2],af[0][3], qa.x, qa.y);
        mma16816(sa0,sa1,sa2,sa3, af[0][0],af[0][1],af[0][2],af[0][3], qa.z, qa.w);
        mma16816(sa0,sa1,sa2,sa3, af[1][0],af[1][1],af[1][2],af[1][3], qa.x, qa.y);
        mma16816(pb0,pb1,pb2,pb3, af[0][0],af[0][1],af[0][2],af[0][3], qb.x, qb.y);
        mma16816(sb0,sb1,sb2,sb3, af[0][0],af[0][1],af[0][2],af[0][3], qb.z, qb.w);
        mma16816(sb0,sb1,sb2,sb3, af[1][0],af[1][1],af[1][2],af[1][3], qb.x, qb.y);

        // row n0: values tileA cols (par0,par1), tileB cols (par0,par1)
        {
            const float f0 = embed(pa0 + sa0, cb);
            const float f1 = embed(pa1 + sa1, cb - 1u);
            const float f2 = embed(pb0 + sb0, cb - 2u);
            const float f3 = embed(pb1 + sb1, cb - 3u);
            const float m01 = fmaxf(f0, f1), n01 = fminf(f0, f1);
            const float m23 = fmaxf(f2, f3), n23 = fminf(f2, f3);
            const float gm = fmaxf(m01, m23);
            const float gs = fmaxf(fminf(m01, m23), fmaxf(n01, n23));
            sec0  = fmaxf(sec0, fmaxf(fminf(best0, gm), gs));
            best0 = fmaxf(best0, gm);
        }
        // row n1
        {
            const float f0 = embed(pa2 + sa2, cb);
            const float f1 = embed(pa3 + sa3, cb - 1u);
            const float f2 = embed(pb2 + sb2, cb - 2u);
            const float f3 = embed(pb3 + sb3, cb - 3u);
            const float m01 = fmaxf(f0, f1), n01 = fminf(f0, f1);
            const float m23 = fmaxf(f2, f3), n23 = fminf(f2, f3);
            const float gm = fmaxf(m01, m23);
            const float gs = fmaxf(fminf(m01, m23), fmaxf(n01, n23));
            sec1  = fmaxf(sec1, fmaxf(fminf(best1, gm), gs));
            best1 = fmaxf(best1, gm);
        }
    }

    // ---- recover this lane's column from embedded code ----
    // pos = 255 - code; col = (pos>>1)*8 + 2t + (pos&1)
    const uint32_t pos0 = 255u - (__float_as_uint(best0) & 255u);
    const uint32_t pos1 = 255u - (__float_as_uint(best1) & 255u);
    int col0 = (int)((pos0 >> 1) * 8 + (pos0 & 1)) + 2 * t;
    int col1 = (int)((pos1 >> 1) * 8 + (pos1 & 1)) + 2 * t;
    const float myb0 = best0, myb1 = best1;

    // ---- 4-lane butterfly on (best, sec); values only ----
    #pragma unroll
    for (int m = 1; m <= 2; m <<= 1) {
        const float ob0 = __shfl_xor_sync(0xffffffffu, best0, m);
        const float os0 = __shfl_xor_sync(0xffffffffu, sec0,  m);
        sec0  = fmaxf(fminf(best0, ob0), fmaxf(sec0, os0));
        best0 = fmaxf(best0, ob0);
        const float ob1 = __shfl_xor_sync(0xffffffffu, best1, m);
        const float os1 = __shfl_xor_sync(0xffffffffu, sec1,  m);
        sec1  = fmaxf(fminf(best1, ob1), fmaxf(sec1, os1));
        best1 = fmaxf(best1, ob1);
    }
    // owner lane(s) of global best contribute their column; min wins (first occ.)
    int cand0 = (myb0 == best0) ? col0 : 0x7fffffff;
    int cand1 = (myb1 == best1) ? col1 : 0x7fffffff;
    #pragma unroll
    for (int m = 1; m <= 2; m <<= 1) {
        cand0 = min(cand0, __shfl_xor_sync(0xffffffffu, cand0, m));
        cand1 = min(cand1, __shfl_xor_sync(0xffffffffu, cand1, m));
    }

    if (t == 0) {
        out[n0] = (float)cand0;
        out[n1] = (float)cand1;
        // strip codes; flag if quantized gap under inflated margin
        const float bq0 = __uint_as_float(__float_as_uint(best0) & 0xFFFFFF00u);
        const float sq0 = __uint_as_float(__float_as_uint(sec0)  & 0xFFFFFF00u);
        const float bq1 = __uint_as_float(__float_as_uint(best1) & 0xFFFFFF00u);
        const float sq1 = __uint_as_float(__float_as_uint(sec1)  & 0xFFFFFF00u);
        if (bq0 - sq0 < MARGINQ) sflag[atomicAdd(&scount, 1)] = n0;
        if (bq1 - sq1 < MARGINQ) sflag[atomicAdd(&scount, 1)] = n1;
    }
    __syncthreads();

    // ---- in-CTA exact rescue for flagged rows (verbatim R5 fp32 chain) ----
    const int cnt = scount;
    if (cnt == 0) return;

    float* rval = (float*)smem;                 // aliases B staging (done with it)
    int*   ridx = (int*)(smem + TPB * 4);

    for (int f = 0; f < cnt; ++f) {
        const int n = sflag[f];

        float a[KK];
        float s = 0.f;
        #pragma unroll
        for (int k = 0; k < KK; ++k) { a[k] = x[k * NTOT + n]; s += a[k]; }
        const float mu = s * (1.0f / KK);
        float ss = 0.f;
        #pragma unroll
        for (int k = 0; k < KK; ++k) { a[k] -= mu; ss += a[k] * a[k]; }
        const float inv = 1.0f / (sqrtf(ss) + 1e-10f);
        #pragma unroll
        for (int k = 0; k < KK; ++k) a[k] *= inv;

        float best = -3.0e38f;
        int   bi   = 0;
        #pragma unroll
        for (int j = 0; j < 4; ++j) {
            const int d = tid * 4 + j;          // ascending within thread
            const float4* bp = (const float4*)(&g_bnorm[d * KK]);
            const float4 w0 = bp[0], w1 = bp[1], w2 = bp[2], w3 = bp[3];
            float acc = 0.f;
            acc = fmaf(a[0],  w0.x, acc); acc = fmaf(a[1],  w0.y, acc);
            acc = fmaf(a[2],  w0.z, acc); acc = fmaf(a[3],  w0.w, acc);
            acc = fmaf(a[4],  w1.x, acc); acc = fmaf(a[5],  w1.y, acc);
            acc = fmaf(a[6],  w1.z, acc); acc = fmaf(a[7],  w1.w, acc);
            acc = fmaf(a[8],  w2.x, acc); acc = fmaf(a[9],  w2.y, acc);
            acc = fmaf(a[10], w2.z, acc); acc = fmaf(a[11], w2.w, acc);
            acc = fmaf(a[12], w3.x, acc); acc = fmaf(a[13], w3.y, acc);
            acc = fmaf(a[14], w3.z, acc); acc = fmaf(a[15], w3.w, acc);
            if (acc > best) { best = acc; bi = d; }   // strict > = first occurrence
        }
        rval[tid] = best;
        ridx[tid] = bi;
        __syncthreads();
        #pragma unroll
        for (int sdt = TPB / 2; sdt >= 1; sdt >>= 1) {
            if (tid < sdt) {
                const float ov = rval[tid + sdt];
                const int   oi = ridx[tid + sdt];
                if (ov > rval[tid] || (ov == rval[tid] && oi < ridx[tid])) {
                    rval[tid] = ov;
                    ridx[tid] = oi;
                }
            }
            __syncthreads();
        }
        if (tid == 0) out[n] = (float)ridx[0];
        __syncthreads();
    }
}

extern "C" void kernel_launch(void* const* d_in, const int* in_sizes, int n_in,
                              void* d_out, int out_size)
{
    const float* x;
    const float* cmat;
    if (in_sizes[0] >= in_sizes[1]) {
        x    = (const float*)d_in[0];
        cmat = (const float*)d_in[1];
    } else {
        x    = (const float*)d_in[1];
        cmat = (const float*)d_in[0];
    }
    float* out = (float*)d_out;

    prep_kernel<<<NTOT / 256 + DD / 256, 256>>>(x, cmat);

    const int smem = DD * 32 * 2;   // 64 KB
    cudaFuncSetAttribute(ncc_hmma_kernel,
                         cudaFuncAttributeMaxDynamicSharedMemorySize, smem);
    ncc_hmma_kernel<<<NBLK, TPB, smem>>>(x, out);
}

// round 16
// speedup vs baseline: 1.9733x; 1.0099x over previous
#include <cuda_runtime.h>
#include <cuda_bf16.h>
#include <cstdint>

// NCCLayer argmax: 2-way bf16 split HMMA + mantissa-embedded-index argmax +
// in-CTA exact rescue. R15 (78.6us) was latency-bound at occ 33.5% (64KB smem
// => 3 CTAs/SM). R16: two-phase 32KB B staging (=> 5 CTAs/SM, ~62% occ) and
// bias folded into MMA accumulator init (embed = 1 LOP3). Margin/rescue
// machinery byte-identical to three consecutive rel_err==0 rounds.

#define KK    16
#define DD    1024
#define NTOT  131072
#define TPB   256          // 8 warps, 128 n-rows per CTA
#define NBLK  (NTOT / 128)
#define MARGINQ 3e-4f      // >= 2*delta_mma (~3.3e-5) + 2*quant (1.22e-4)

__device__ __nv_bfloat16 g_as[2][NTOT * KK];   // A splits, n-major (8 MB)
__device__ __nv_bfloat16 g_bsp[DD * 32];       // B interleaved frag-pack (64 KB)
__device__ float g_bnorm[DD * KK];             // exact fp32 normalized b, [d][k]

// ---------------- fused prep: normalize + 2-way bf16 split ----------------
__device__ __forceinline__ void split2(float v, __nv_bfloat16& h1, __nv_bfloat16& h2) {
    h1 = __float2bfloat16(v);
    h2 = __float2bfloat16(v - __bfloat162float(h1));
}
__device__ __forceinline__ uint32_t pkbf(__nv_bfloat16 lo, __nv_bfloat16 hi) {
    return (uint32_t)__bfloat16_as_ushort(lo) | ((uint32_t)__bfloat16_as_ushort(hi) << 16);
}

__global__ __launch_bounds__(256) void prep_kernel(
    const float* __restrict__ x,
    const float* __restrict__ cmat)
{
    const int tid = threadIdx.x;
    if (blockIdx.x < NTOT / 256) {
        // ---- A side ----
        const int n = blockIdx.x * 256 + tid;
        float a[KK];
        float s = 0.f;
        #pragma unroll
        for (int k = 0; k < KK; ++k) { a[k] = x[k * NTOT + n]; s += a[k]; }
        const float mu = s * (1.0f / KK);
        float ss = 0.f;
        #pragma unroll
        for (int k = 0; k < KK; ++k) { a[k] -= mu; ss += a[k] * a[k]; }
        const float inv = 1.0f / (sqrtf(ss) + 1e-10f);
        __nv_bfloat16 h1[KK], h2[KK];
        #pragma unroll
        for (int k = 0; k < KK; ++k) split2(a[k] * inv, h1[k], h2[k]);
        uint4* d0 = (uint4*)&g_as[0][n * KK];
        uint4* d1 = (uint4*)&g_as[1][n * KK];
        d0[0] = make_uint4(pkbf(h1[0],h1[1]), pkbf(h1[2],h1[3]), pkbf(h1[4],h1[5]), pkbf(h1[6],h1[7]));
        d0[1] = make_uint4(pkbf(h1[8],h1[9]), pkbf(h1[10],h1[11]), pkbf(h1[12],h1[13]), pkbf(h1[14],h1[15]));
        d1[0] = make_uint4(pkbf(h2[0],h2[1]), pkbf(h2[2],h2[3]), pkbf(h2[4],h2[5]), pkbf(h2[6],h2[7]));
        d1[1] = make_uint4(pkbf(h2[8],h2[9]), pkbf(h2[10],h2[11]), pkbf(h2[12],h2[13]), pkbf(h2[14],h2[15]));
    } else {
        // ---- B side ----
        const int d = (blockIdx.x - NTOT / 256) * 256 + tid;
        float b[KK];
        float s = 0.f;
        #pragma unroll
        for (int k = 0; k < KK; ++k) { b[k] = cmat[k * DD + d]; s += b[k]; }
        const float mu = s * (1.0f / KK);
        float ss = 0.f;
        #pragma unroll
        for (int k = 0; k < KK; ++k) { b[k] -= mu; ss += b[k] * b[k]; }
        const float inv = 1.0f / (sqrtf(ss) + 1e-10f);
        float bn[KK];
        __nv_bfloat16 lb[32];
        #pragma unroll
        for (int k = 0; k < KK; ++k) {
            bn[k] = b[k] * inv;               // same op chain as R5 exact kernel
            __nv_bfloat16 h1, h2;
            split2(bn[k], h1, h2);
            // interleaved frag-pack: quad p = (k&7)>>1; 16B = [s0 x4 | s1 x4]
            const int p    = (k & 7) >> 1;
            const int slot = ((k >> 3) << 1) | (k & 1);
            lb[p * 8 + 0 + slot] = h1;
            lb[p * 8 + 4 + slot] = h2;
        }
        float4* fb = (float4*)&g_bnorm[d * KK];
        fb[0] = make_float4(bn[0], bn[1], bn[2], bn[3]);
        fb[1] = make_float4(bn[4], bn[5], bn[6], bn[7]);
        fb[2] = make_float4(bn[8], bn[9], bn[10], bn[11]);
        fb[3] = make_float4(bn[12], bn[13], bn[14], bn[15]);
        uint4* ob = (uint4*)&g_bsp[d * 32];
        #pragma unroll
        for (int q = 0; q < 4; ++q)
            ob[q] = make_uint4(pkbf(lb[q*8+0],lb[q*8+1]), pkbf(lb[q*8+2],lb[q*8+3]),
                               pkbf(lb[q*8+4],lb[q*8+5]), pkbf(lb[q*8+6],lb[q*8+7]));
    }
}

// ---------------- main: HMMA + embedded-index top-2 + in-CTA rescue ----------------
__device__ __forceinline__ void mma16816(float& d0, float& d1, float& d2, float& d3,
                                         uint32_t a0, uint32_t a1, uint32_t a2,
                                         uint32_t a3, uint32_t b0, uint32_t b1) {
    asm volatile(
        "mma.sync.aligned.m16n8k16.row.col.f32.bf16.bf16.f32 "
        "{%0,%1,%2,%3}, {%4,%5,%6,%7}, {%8,%9}, {%0,%1,%2,%3};"
        : "+f"(d0), "+f"(d1), "+f"(d2), "+f"(d3)
        : "r"(a0), "r"(a1), "r"(a2), "r"(a3), "r"(b0), "r"(b1));
}

// value already biased positive (+4 via accumulator init): pure bit-splice
__device__ __forceinline__ float embed(float v, uint32_t code) {
    return __uint_as_float((__float_as_uint(v) & 0xFFFFFF00u) | code);
}

__global__ __launch_bounds__(TPB) void ncc_hmma_kernel(
    const float* __restrict__ x,
    float* __restrict__ out)
{
    __shared__ char smem[512 * 64];  // half of B frag-pack (32 KB), two phases
    __shared__ int scount;
    __shared__ int sflag[128];

    const int tid = threadIdx.x;
    const int wid = tid >> 5;
    const int lid = tid & 31;
    const int t   = lid & 3;     // quad pos
    const int r   = lid >> 2;    // group row / B col

    if (tid == 0) scount = 0;

    // ---- A fragments (rows n0 = base+r, n1 = n0+8), 2 splits ----
    const int nbase = blockIdx.x * 128 + wid * 16;
    const int n0 = nbase + r;
    const int n1 = n0 + 8;
    uint32_t af[2][4];
    #pragma unroll
    for (int s = 0; s < 2; ++s) {
        af[s][0] = *(const uint32_t*)&g_as[s][n0 * KK + 2 * t];
        af[s][1] = *(const uint32_t*)&g_as[s][n1 * KK + 2 * t];
        af[s][2] = *(const uint32_t*)&g_as[s][n0 * KK + 2 * t + 8];
        af[s][3] = *(const uint32_t*)&g_as[s][n1 * KK + 2 * t + 8];
    }

    // embedded running top-2 per row (positive domain; 0.0 < any value)
    float best0 = 0.f, sec0 = 0.f;
    float best1 = 0.f, sec1 = 0.f;

    #pragma unroll
    for (int ph = 0; ph < 2; ++ph) {
        // ---- Stage this phase's 512 columns (32 KB) ----
        if (ph > 0) __syncthreads();     // all warps done reading previous phase
        {
            const uint4* src = (const uint4*)&g_bsp[ph * 512 * 32];
            uint4* dst = (uint4*)smem;
            #pragma unroll
            for (int i = 0; i < (512 * 64) / 16 / TPB; ++i)
                dst[tid + i * TPB] = src[tid + i * TPB];
        }
        __syncthreads();

        #pragma unroll 4
        for (int dt2 = 0; dt2 < 32; ++dt2) {     // 2 tiles per iteration
            const int dgl = dt2 * 16;            // local col within phase
            const uint32_t cb = 255u - 4u * (uint32_t)(ph * 32 + dt2);

            const uint4 qa = *(const uint4*)(smem + (dgl + r) * 64 + t * 16);
            const uint4 qb = *(const uint4*)(smem + (dgl + 8 + r) * 64 + t * 16);

            // big-term accumulators start at +4.0 => bias is free
            float pa0=4.f,pa1=4.f,pa2=4.f,pa3=4.f, sa0=0.f,sa1=0.f,sa2=0.f,sa3=0.f;
            float pb0=4.f,pb1=4.f,pb2=4.f,pb3=4.f, sb0=0.f,sb1=0.f,sb2=0.f,sb3=0.f;
            mma16816(pa0,pa1,pa2,pa3, af[0][0],af[0][1],af[0][2],af[0][3], qa.x, qa.y);
            mma16816(sa0,sa1,sa2,sa3, af[0][0],af[0][1],af[0][2],af[0][3], qa.z, qa.w);
            mma16816(sa0,sa1,sa2,sa3, af[1][0],af[1][1],af[1][2],af[1][3], qa.x, qa.y);
            mma16816(pb0,pb1,pb2,pb3, af[0][0],af[0][1],af[0][2],af[0][3], qb.x, qb.y);
            mma16816(sb0,sb1,sb2,sb3, af[0][0],af[0][1],af[0][2],af[0][3], qb.z, qb.w);
            mma16816(sb0,sb1,sb2,sb3, af[1][0],af[1][1],af[1][2],af[1][3], qb.x, qb.y);

            // row n0
            {
                const float f0 = embed(pa0 + sa0, cb);
                const float f1 = embed(pa1 + sa1, cb - 1u);
                const float f2 = embed(pb0 + sb0, cb - 2u);
                const float f3 = embed(pb1 + sb1, cb - 3u);
                const float m01 = fmaxf(f0, f1), n01 = fminf(f0, f1);
                const float m23 = fmaxf(f2, f3), n23 = fminf(f2, f3);
                const float gm = fmaxf(m01, m23);
                const float gs = fmaxf(fminf(m01, m23), fmaxf(n01, n23));
                sec0  = fmaxf(sec0, fmaxf(fminf(best0, gm), gs));
                best0 = fmaxf(best0, gm);
            }
            // row n1
            {
                const float f0 = embed(pa2 + sa2, cb);
                const float f1 = embed(pa3 + sa3, cb - 1u);
                const float f2 = embed(pb2 + sb2, cb - 2u);
                const float f3 = embed(pb3 + sb3, cb - 3u);
                const float m01 = fmaxf(f0, f1), n01 = fminf(f0, f1);
                const float m23 = fmaxf(f2, f3), n23 = fminf(f2, f3);
                const float gm = fmaxf(m01, m23);
                const float gs = fmaxf(fminf(m01, m23), fmaxf(n01, n23));
                sec1  = fmaxf(sec1, fmaxf(fminf(best1, gm), gs));
                best1 = fmaxf(best1, gm);
            }
        }
    }

    // ---- recover this lane's column from embedded code ----
    // pos = 255 - code; col = (pos>>1)*8 + 2t + (pos&1)
    const uint32_t pos0 = 255u - (__float_as_uint(best0) & 255u);
    const uint32_t pos1 = 255u - (__float_as_uint(best1) & 255u);
    int col0 = (int)((pos0 >> 1) * 8 + (pos0 & 1)) + 2 * t;
    int col1 = (int)((pos1 >> 1) * 8 + (pos1 & 1)) + 2 * t;
    const float myb0 = best0, myb1 = best1;

    // ---- 4-lane butterfly on (best, sec); values only ----
    #pragma unroll
    for (int m = 1; m <= 2; m <<= 1) {
        const float ob0 = __shfl_xor_sync(0xffffffffu, best0, m);
        const float os0 = __shfl_xor_sync(0xffffffffu, sec0,  m);
        sec0  = fmaxf(fminf(best0, ob0), fmaxf(sec0, os0));
        best0 = fmaxf(best0, ob0);
        const float ob1 = __shfl_xor_sync(0xffffffffu, best1, m);
        const float os1 = __shfl_xor_sync(0xffffffffu, sec1,  m);
        sec1  = fmaxf(fminf(best1, ob1), fmaxf(sec1, os1));
        best1 = fmaxf(best1, ob1);
    }
    // owner lane(s) of global best contribute their column; min wins (first occ.)
    int cand0 = (myb0 == best0) ? col0 : 0x7fffffff;
    int cand1 = (myb1 == best1) ? col1 : 0x7fffffff;
    #pragma unroll
    for (int m = 1; m <= 2; m <<= 1) {
        cand0 = min(cand0, __shfl_xor_sync(0xffffffffu, cand0, m));
        cand1 = min(cand1, __shfl_xor_sync(0xffffffffu, cand1, m));
    }

    if (t == 0) {
        out[n0] = (float)cand0;
        out[n1] = (float)cand1;
        // strip codes; flag if quantized gap under inflated margin
        const float bq0 = __uint_as_float(__float_as_uint(best0) & 0xFFFFFF00u);
        const float sq0 = __uint_as_float(__float_as_uint(sec0)  & 0xFFFFFF00u);
        const float bq1 = __uint_as_float(__float_as_uint(best1) & 0xFFFFFF00u);
        const float sq1 = __uint_as_float(__float_as_uint(sec1)  & 0xFFFFFF00u);
        if (bq0 - sq0 < MARGINQ) sflag[atomicAdd(&scount, 1)] = n0;
        if (bq1 - sq1 < MARGINQ) sflag[atomicAdd(&scount, 1)] = n1;
    }
    __syncthreads();

    // ---- in-CTA exact rescue for flagged rows (verbatim R5 fp32 chain) ----
    const int cnt = scount;
    if (cnt == 0) return;

    float* rval = (float*)smem;                 // aliases B staging (done with it)
    int*   ridx = (int*)(smem + TPB * 4);

    for (int f = 0; f < cnt; ++f) {
        const int n = sflag[f];

        float a[KK];
        float s = 0.f;
        #pragma unroll
        for (int k = 0; k < KK; ++k) { a[k] = x[k * NTOT + n]; s += a[k]; }
        const float mu = s * (1.0f / KK);
        float ss = 0.f;
        #pragma unroll
        for (int k = 0; k < KK; ++k) { a[k] -= mu; ss += a[k] * a[k]; }
        const float inv = 1.0f / (sqrtf(ss) + 1e-10f);
        #pragma unroll
        for (int k = 0; k < KK; ++k) a[k] *= inv;

        float best = -3.0e38f;
        int   bi   = 0;
        #pragma unroll
        for (int j = 0; j < 4; ++j) {
            const int d = tid * 4 + j;          // ascending within thread
            const float4* bp = (const float4*)(&g_bnorm[d * KK]);
            const float4 w0 = bp[0], w1 = bp[1], w2 = bp[2], w3 = bp[3];
            float acc = 0.f;
            acc = fmaf(a[0],  w0.x, acc); acc = fmaf(a[1],  w0.y, acc);
            acc = fmaf(a[2],  w0.z, acc); acc = fmaf(a[3],  w0.w, acc);
            acc = fmaf(a[4],  w1.x, acc); acc = fmaf(a[5],  w1.y, acc);
            acc = fmaf(a[6],  w1.z, acc); acc = fmaf(a[7],  w1.w, acc);
            acc = fmaf(a[8],  w2.x, acc); acc = fmaf(a[9],  w2.y, acc);
            acc = fmaf(a[10], w2.z, acc); acc = fmaf(a[11], w2.w, acc);
            acc = fmaf(a[12], w3.x, acc); acc = fmaf(a[13], w3.y, acc);
            acc = fmaf(a[14], w3.z, acc); acc = fmaf(a[15], w3.w, acc);
            if (acc > best) { best = acc; bi = d; }   // strict > = first occurrence
        }
        rval[tid] = best;
        ridx[tid] = bi;
        __syncthreads();
        #pragma unroll
        for (int sdt = TPB / 2; sdt >= 1; sdt >>= 1) {
            if (tid < sdt) {
                const float ov = rval[tid + sdt];
                const int   oi = ridx[tid + sdt];
                if (ov > rval[tid] || (ov == rval[tid] && oi < ridx[tid])) {
                    rval[tid] = ov;
                    ridx[tid] = oi;
                }
            }
            __syncthreads();
        }
        if (tid == 0) out[n] = (float)ridx[0];
        __syncthreads();
    }
}

extern "C" void kernel_launch(void* const* d_in, const int* in_sizes, int n_in,
                              void* d_out, int out_size)
{
    const float* x;
    const float* cmat;
    if (in_sizes[0] >= in_sizes[1]) {
        x    = (const float*)d_in[0];
        cmat = (const float*)d_in[1];
    } else {
        x    = (const float*)d_in[1];
        cmat = (const float*)d_in[0];
    }
    float* out = (float*)d_out;

    prep_kernel<<<NTOT / 256 + DD / 256, 256>>>(x, cmat);
    ncc_hmma_kernel<<<NBLK, TPB>>>(x, out);
}